// round 1
// baseline (speedup 1.0000x reference)
#include <cuda_runtime.h>
#include <cuda_bf16.h>

// Scalar accumulator in device global memory (no allocations allowed).
__device__ double g_mse_sum;

__global__ void mse_zero_kernel() {
    g_mse_sum = 0.0;
}

// Each thread processes PAIRS of rows: 2 rows * 10 floats = 80 bytes = 5 float4,
// 16B-aligned for both arrays. Fully vectorized, coalesced loads.
__global__ void mse_main_kernel(const float4* __restrict__ o4,
                                const float4* __restrict__ l4,
                                long long pairs, int n_rows,
                                const float* __restrict__ o_f,
                                const float* __restrict__ l_f) {
    float acc = 0.0f;

    const long long stride = (long long)gridDim.x * blockDim.x;
    for (long long p = (long long)blockIdx.x * blockDim.x + threadIdx.x;
         p < pairs; p += stride) {
        float4 ov0 = o4[p * 5 + 0];
        float4 ov1 = o4[p * 5 + 1];
        float4 ov2 = o4[p * 5 + 2];
        float4 ov3 = o4[p * 5 + 3];
        float4 ov4 = o4[p * 5 + 4];
        float4 lv0 = l4[p * 5 + 0];
        float4 lv1 = l4[p * 5 + 1];
        float4 lv2 = l4[p * 5 + 2];
        float4 lv3 = l4[p * 5 + 3];
        float4 lv4 = l4[p * 5 + 4];

        float o[20] = {ov0.x, ov0.y, ov0.z, ov0.w,
                       ov1.x, ov1.y, ov1.z, ov1.w,
                       ov2.x, ov2.y, ov2.z, ov2.w,
                       ov3.x, ov3.y, ov3.z, ov3.w,
                       ov4.x, ov4.y, ov4.z, ov4.w};
        float l[20] = {lv0.x, lv0.y, lv0.z, lv0.w,
                       lv1.x, lv1.y, lv1.z, lv1.w,
                       lv2.x, lv2.y, lv2.z, lv2.w,
                       lv3.x, lv3.y, lv3.z, lv3.w,
                       lv4.x, lv4.y, lv4.z, lv4.w};

        // Row 0: class id is l[0]; ncols = 1 + 3*cls  (COUNTS = {1,4,7,10})
        int nc0 = 1 + 3 * __float2int_rn(l[0]);
        #pragma unroll
        for (int j = 0; j < 10; j++) {
            float d = o[j] - l[j];
            acc += (j < nc0) ? d * d : 0.0f;
        }

        // Row 1
        int nc1 = 1 + 3 * __float2int_rn(l[10]);
        #pragma unroll
        for (int j = 0; j < 10; j++) {
            float d = o[10 + j] - l[10 + j];
            acc += (j < nc1) ? d * d : 0.0f;
        }
    }

    // Odd-row tail (n_rows odd): one designated thread does it scalar.
    if ((n_rows & 1) &&
        blockIdx.x == 0 && threadIdx.x == 0) {
        long long r = (long long)n_rows - 1;
        const float* orow = o_f + r * 10;
        const float* lrow = l_f + r * 10;
        int nc = 1 + 3 * __float2int_rn(lrow[0]);
        #pragma unroll
        for (int j = 0; j < 10; j++) {
            float d = orow[j] - lrow[j];
            acc += (j < nc) ? d * d : 0.0f;
        }
    }

    // Warp reduce
    #pragma unroll
    for (int off = 16; off > 0; off >>= 1)
        acc += __shfl_xor_sync(0xFFFFFFFFu, acc, off);

    // Block reduce via shared
    __shared__ float warp_sums[32];
    int lane = threadIdx.x & 31;
    int wid  = threadIdx.x >> 5;
    if (lane == 0) warp_sums[wid] = acc;
    __syncthreads();

    int nwarps = (blockDim.x + 31) >> 5;
    if (wid == 0) {
        float v = (lane < nwarps) ? warp_sums[lane] : 0.0f;
        #pragma unroll
        for (int off = 16; off > 0; off >>= 1)
            v += __shfl_xor_sync(0xFFFFFFFFu, v, off);
        if (lane == 0)
            atomicAdd(&g_mse_sum, (double)v);
    }
}

__global__ void mse_finalize_kernel(float* __restrict__ out, int n_rows) {
    out[0] = (float)(g_mse_sum / (double)n_rows);
}

extern "C" void kernel_launch(void* const* d_in, const int* in_sizes, int n_in,
                              void* d_out, int out_size) {
    const float* outputs = (const float*)d_in[0];
    const float* labels  = (const float*)d_in[1];
    float* out = (float*)d_out;

    int n_rows = in_sizes[0] / 10;
    long long pairs = (long long)n_rows / 2;

    mse_zero_kernel<<<1, 1>>>();

    const int threads = 256;
    int blocks = 148 * 8;  // ~2 waves of 4 CTAs/SM; grid-stride covers the rest
    long long need = (pairs + threads - 1) / threads;
    if ((long long)blocks > need) blocks = (int)(need > 0 ? need : 1);

    mse_main_kernel<<<blocks, threads>>>(
        (const float4*)outputs, (const float4*)labels,
        pairs, n_rows, outputs, labels);

    mse_finalize_kernel<<<1, 1>>>(out, n_rows);
}